// round 2
// baseline (speedup 1.0000x reference)
#include <cuda_runtime.h>

// Problem constants (from reference)
#define NB        16      // batch pairs
#define N_TOT     16384   // total rows (src+ref interleaved)
#define PPT       128     // points per object
#define FEAT      256
#define EMB       100
#define OUTW      200     // output row width: [0,100)=sg_out, [100,200)=pt_out

__device__ __forceinline__ void fma4(float* acc, float s, float4 wv) {
    acc[0] = fmaf(s, wv.x, acc[0]);
    acc[1] = fmaf(s, wv.y, acc[1]);
    acc[2] = fmaf(s, wv.z, acc[2]);
    acc[3] = fmaf(s, wv.w, acc[3]);
}

// ---------------------------------------------------------------------------
// Point branch: per block = one object (128 points).
//   h1 = relu(pts(128x3) @ W1(3x64) + b1)
//   h2 = relu(h1 @ W2(64x128) + b2)
//   h3 = h2 @ W3(128x256)            (b3 folded in after max)
//   feat = max_p h3 + b3 ; pt_out = feat @ oe_w(256x100) + oe_b
// Points processed in 4 groups of 32 so shared tiles stay < 48KB.
// Layer2/3 are register-tiled GEMMs (8 pts x 4/8 outs per thread).
// ---------------------------------------------------------------------------
__global__ __launch_bounds__(128) void point_branch_kernel(
    const float* __restrict__ pts,   // (N_TOT, 128, 3)
    const float* __restrict__ w1,    // (3, 64)
    const float* __restrict__ b1,    // (64)
    const float* __restrict__ w2,    // (64, 128)
    const float* __restrict__ b2,    // (128)
    const float* __restrict__ w3,    // (128, 256)
    const float* __restrict__ b3,    // (256)
    const float* __restrict__ oew,   // (256, 100)
    const float* __restrict__ oeb,   // (100)
    float* __restrict__ out)         // (N_TOT, 200)
{
    __shared__ float h1t[32 * 68];    // 32 pts x 64 (pad 68)   8.7 KB
    __shared__ float h2t[32 * 132];   // 32 pts x 128 (pad 132) 16.9 KB
    __shared__ float red[4 * 256];    // per-ty running max      4 KB
    __shared__ float feat_s[256];

    const int n  = blockIdx.x;
    const int t  = threadIdx.x;
    const int tx = t & 31;
    const int ty = t >> 5;

    float runmax[8];
#pragma unroll
    for (int o = 0; o < 8; ++o) runmax[o] = -1e30f;

    const float4 b2v = *(const float4*)(b2 + tx * 4);

    for (int pg = 0; pg < 4; ++pg) {
        __syncthreads();  // protect h1t/h2t reuse across pg iterations

        // ---- layer 1: 32 points of this group; thread (pl, jq): 16 outputs
        {
            const int pl = t & 31;
            const int j0 = (t >> 5) * 16;
            const size_t pb = ((size_t)n * PPT + (size_t)pg * 32 + pl) * 3;
            const float x = pts[pb + 0];
            const float y = pts[pb + 1];
            const float z = pts[pb + 2];
#pragma unroll
            for (int j = 0; j < 16; j += 4) {
                const int jj = j0 + j;
                float4 v;
                v.x = fmaf(x, __ldg(w1 + jj + 0), fmaf(y, __ldg(w1 + 64 + jj + 0), fmaf(z, __ldg(w1 + 128 + jj + 0), __ldg(b1 + jj + 0))));
                v.y = fmaf(x, __ldg(w1 + jj + 1), fmaf(y, __ldg(w1 + 64 + jj + 1), fmaf(z, __ldg(w1 + 128 + jj + 1), __ldg(b1 + jj + 1))));
                v.z = fmaf(x, __ldg(w1 + jj + 2), fmaf(y, __ldg(w1 + 64 + jj + 2), fmaf(z, __ldg(w1 + 128 + jj + 2), __ldg(b1 + jj + 2))));
                v.w = fmaf(x, __ldg(w1 + jj + 3), fmaf(y, __ldg(w1 + 64 + jj + 3), fmaf(z, __ldg(w1 + 128 + jj + 3), __ldg(b1 + jj + 3))));
                v.x = fmaxf(v.x, 0.0f);
                v.y = fmaxf(v.y, 0.0f);
                v.z = fmaxf(v.z, 0.0f);
                v.w = fmaxf(v.w, 0.0f);
                *(float4*)&h1t[pl * 68 + jj] = v;
            }
        }
        __syncthreads();

        // ---- layer 2: H2(32x128) = relu(H1(32x64) @ W2(64x128))
        // thread tile: 8 pts (p0 = ty*8) x 4 outs (tx*4)
        {
            const int p0 = ty * 8;
            float acc[8][4];
#pragma unroll
            for (int i = 0; i < 8; ++i) {
                acc[i][0] = b2v.x; acc[i][1] = b2v.y;
                acc[i][2] = b2v.z; acc[i][3] = b2v.w;
            }
#pragma unroll 2
            for (int k = 0; k < 64; k += 4) {
                float4 a[8];
#pragma unroll
                for (int i = 0; i < 8; ++i)
                    a[i] = *(const float4*)&h1t[(p0 + i) * 68 + k];
                float4 wv[4];
#pragma unroll
                for (int q = 0; q < 4; ++q)
                    wv[q] = __ldg((const float4*)(w2 + (size_t)(k + q) * 128 + tx * 4));
#pragma unroll
                for (int i = 0; i < 8; ++i) {
                    fma4(acc[i], a[i].x, wv[0]);
                    fma4(acc[i], a[i].y, wv[1]);
                    fma4(acc[i], a[i].z, wv[2]);
                    fma4(acc[i], a[i].w, wv[3]);
                }
            }
#pragma unroll
            for (int i = 0; i < 8; ++i) {
                float4 v;
                v.x = fmaxf(acc[i][0], 0.0f);
                v.y = fmaxf(acc[i][1], 0.0f);
                v.z = fmaxf(acc[i][2], 0.0f);
                v.w = fmaxf(acc[i][3], 0.0f);
                *(float4*)&h2t[(p0 + i) * 132 + tx * 4] = v;
            }
        }
        __syncthreads();

        // ---- layer 3: H3(32x256) = H2(32x128) @ W3(128x256), fold into runmax
        // thread tile: 8 pts (p0 = ty*8) x 8 outs (tx*8)
        {
            const int p0 = ty * 8;
            float acc[8][8];
#pragma unroll
            for (int i = 0; i < 8; ++i)
#pragma unroll
                for (int o = 0; o < 8; ++o) acc[i][o] = 0.0f;

#pragma unroll 1
            for (int k = 0; k < 128; k += 4) {
                float4 a[8];
#pragma unroll
                for (int i = 0; i < 8; ++i)
                    a[i] = *(const float4*)&h2t[(p0 + i) * 132 + k];
                float4 wa[4], wb[4];
#pragma unroll
                for (int q = 0; q < 4; ++q) {
                    const float* wrow = w3 + (size_t)(k + q) * 256 + tx * 8;
                    wa[q] = __ldg((const float4*)(wrow + 0));
                    wb[q] = __ldg((const float4*)(wrow + 4));
                }
#pragma unroll
                for (int i = 0; i < 8; ++i) {
                    fma4(&acc[i][0], a[i].x, wa[0]); fma4(&acc[i][4], a[i].x, wb[0]);
                    fma4(&acc[i][0], a[i].y, wa[1]); fma4(&acc[i][4], a[i].y, wb[1]);
                    fma4(&acc[i][0], a[i].z, wa[2]); fma4(&acc[i][4], a[i].z, wb[2]);
                    fma4(&acc[i][0], a[i].w, wa[3]); fma4(&acc[i][4], a[i].w, wb[3]);
                }
            }
#pragma unroll
            for (int o = 0; o < 8; ++o)
#pragma unroll
                for (int i = 0; i < 8; ++i)
                    runmax[o] = fmaxf(runmax[o], acc[i][o]);
        }
    }

    // ---- reduce running max across ty (4 groups), add b3
#pragma unroll
    for (int o = 0; o < 8; o += 4) {
        float4 v = make_float4(runmax[o], runmax[o + 1], runmax[o + 2], runmax[o + 3]);
        *(float4*)&red[ty * 256 + tx * 8 + o] = v;
    }
    __syncthreads();
#pragma unroll
    for (int o = t; o < 256; o += 128) {
        float m = fmaxf(fmaxf(red[o], red[256 + o]), fmaxf(red[512 + o], red[768 + o]));
        feat_s[o] = m + __ldg(b3 + o);
    }
    __syncthreads();

    // ---- pt_out = feat @ oe_w + oe_b  (100 outputs)
    if (t < EMB) {
        float acc = __ldg(oeb + t);
#pragma unroll 4
        for (int k = 0; k < 256; k += 4) {
            float4 f = *(const float4*)&feat_s[k];
            acc = fmaf(f.x, __ldg(oew + (size_t)(k + 0) * EMB + t), acc);
            acc = fmaf(f.y, __ldg(oew + (size_t)(k + 1) * EMB + t), acc);
            acc = fmaf(f.z, __ldg(oew + (size_t)(k + 2) * EMB + t), acc);
            acc = fmaf(f.w, __ldg(oew + (size_t)(k + 3) * EMB + t), acc);
        }
        out[(size_t)n * OUTW + EMB + t] = acc;
    }
}

// ---------------------------------------------------------------------------
// Node branch: per block = 8 output rows, 256 threads (thread = feature col).
//   gather input row (src/ref per interleave), emb = relu(x@W1+b1)@W2+b2,
//   sg_out = emb @ se_w + se_b -> out cols [0,100)
// ---------------------------------------------------------------------------
__global__ __launch_bounds__(256) void node_branch_kernel(
    const float* __restrict__ srcf,     // (N_SRC, 256)
    const float* __restrict__ reff,     // (N_REF, 256)
    const void*  __restrict__ counts_raw, // (16,2) int64 OR int32
    const float* __restrict__ w1,       // (256,256)
    const float* __restrict__ b1,       // (256)
    const float* __restrict__ w2,       // (256,256)
    const float* __restrict__ b2,       // (256)
    const float* __restrict__ sew,      // (256,100)
    const float* __restrict__ seb,      // (100)
    float* __restrict__ out)            // (N_TOT, 200)
{
    __shared__ float xs[8 * 260];
    __shared__ float hs[8 * 260];
    __shared__ int srow[8];
    __shared__ int sflag[8];

    const int t = threadIdx.x;
    const long long o0 = (long long)blockIdx.x * 8;

    if (t < 8) {
        // Detect int64 vs int32 counts layout (JAX may silently downcast).
        const int* c32 = (const int*)counts_raw;
        const bool is64 = (c32[1] == 0 && c32[3] == 0);
        const long long o = o0 + t;
        long long cum = 0, ssum = 0, rsum = 0, idx = 0;
        int flag = 0;
        for (int b = 0; b < NB; ++b) {
            long long sc, rc;
            if (is64) {
                sc = ((const long long*)counts_raw)[2 * b];
                rc = ((const long long*)counts_raw)[2 * b + 1];
            } else {
                sc = c32[2 * b];
                rc = c32[2 * b + 1];
            }
            const long long tot = sc + rc;
            if (o < cum + tot) {
                const long long off = o - cum;
                if (off < sc) { flag = 0; idx = ssum + off; }
                else          { flag = 1; idx = rsum + (off - sc); }
                break;
            }
            cum += tot; ssum += sc; rsum += rc;
        }
        srow[t]  = (int)idx;
        sflag[t] = flag;
    }
    __syncthreads();

#pragma unroll
    for (int r = 0; r < 8; ++r) {
        const float* base = sflag[r] ? reff : srcf;
        xs[r * 260 + t] = base[(size_t)srow[r] * FEAT + t];
    }
    __syncthreads();

    float acc[8];

    // ---- layer 1: h = relu(x @ W1 + b1), thread owns column t for 8 rows
    {
        const float bv = __ldg(b1 + t);
#pragma unroll
        for (int r = 0; r < 8; ++r) acc[r] = bv;
#pragma unroll 1
        for (int k = 0; k < 256; k += 4) {
            const float w0 = __ldg(w1 + (size_t)(k + 0) * 256 + t);
            const float wq1 = __ldg(w1 + (size_t)(k + 1) * 256 + t);
            const float wq2 = __ldg(w1 + (size_t)(k + 2) * 256 + t);
            const float wq3 = __ldg(w1 + (size_t)(k + 3) * 256 + t);
#pragma unroll
            for (int r = 0; r < 8; ++r) {
                float4 xv = *(const float4*)&xs[r * 260 + k];
                acc[r] = fmaf(xv.x, w0, acc[r]);
                acc[r] = fmaf(xv.y, wq1, acc[r]);
                acc[r] = fmaf(xv.z, wq2, acc[r]);
                acc[r] = fmaf(xv.w, wq3, acc[r]);
            }
        }
#pragma unroll
        for (int r = 0; r < 8; ++r) hs[r * 260 + t] = fmaxf(acc[r], 0.0f);
    }
    __syncthreads();

    // ---- layer 2: e = h @ W2 + b2 (no relu), write into xs buffer
    {
        const float bv = __ldg(b2 + t);
#pragma unroll
        for (int r = 0; r < 8; ++r) acc[r] = bv;
#pragma unroll 1
        for (int k = 0; k < 256; k += 4) {
            const float w0 = __ldg(w2 + (size_t)(k + 0) * 256 + t);
            const float wq1 = __ldg(w2 + (size_t)(k + 1) * 256 + t);
            const float wq2 = __ldg(w2 + (size_t)(k + 2) * 256 + t);
            const float wq3 = __ldg(w2 + (size_t)(k + 3) * 256 + t);
#pragma unroll
            for (int r = 0; r < 8; ++r) {
                float4 xv = *(const float4*)&hs[r * 260 + k];
                acc[r] = fmaf(xv.x, w0, acc[r]);
                acc[r] = fmaf(xv.y, wq1, acc[r]);
                acc[r] = fmaf(xv.z, wq2, acc[r]);
                acc[r] = fmaf(xv.w, wq3, acc[r]);
            }
        }
#pragma unroll
        for (int r = 0; r < 8; ++r) xs[r * 260 + t] = acc[r];
    }
    __syncthreads();

    // ---- sg_out = e @ se_w + se_b (100 cols)
    if (t < EMB) {
        float accs[8];
        const float bv = __ldg(seb + t);
#pragma unroll
        for (int r = 0; r < 8; ++r) accs[r] = bv;
#pragma unroll 1
        for (int k = 0; k < 256; k += 4) {
            const float w0 = __ldg(sew + (size_t)(k + 0) * EMB + t);
            const float wq1 = __ldg(sew + (size_t)(k + 1) * EMB + t);
            const float wq2 = __ldg(sew + (size_t)(k + 2) * EMB + t);
            const float wq3 = __ldg(sew + (size_t)(k + 3) * EMB + t);
#pragma unroll
            for (int r = 0; r < 8; ++r) {
                float4 ev = *(const float4*)&xs[r * 260 + k];
                accs[r] = fmaf(ev.x, w0, accs[r]);
                accs[r] = fmaf(ev.y, wq1, accs[r]);
                accs[r] = fmaf(ev.z, wq2, accs[r]);
                accs[r] = fmaf(ev.w, wq3, accs[r]);
            }
        }
#pragma unroll
        for (int r = 0; r < 8; ++r)
            out[(size_t)(o0 + r) * OUTW + t] = accs[r];
    }
}

extern "C" void kernel_launch(void* const* d_in, const int* in_sizes, int n_in,
                              void* d_out, int out_size)
{
    const float* pts    = (const float*)d_in[0];
    const float* srcf   = (const float*)d_in[1];
    const float* reff   = (const float*)d_in[2];
    const void*  counts = d_in[3];
    // d_in[4] overlap, d_in[5] target: unused by the reference output
    const float* sg_w1  = (const float*)d_in[6];
    const float* sg_b1  = (const float*)d_in[7];
    const float* sg_w2  = (const float*)d_in[8];
    const float* sg_b2  = (const float*)d_in[9];
    const float* se_w   = (const float*)d_in[10];
    const float* se_b   = (const float*)d_in[11];
    const float* p_w1   = (const float*)d_in[12];
    const float* p_b1   = (const float*)d_in[13];
    const float* p_w2   = (const float*)d_in[14];
    const float* p_b2   = (const float*)d_in[15];
    const float* p_w3   = (const float*)d_in[16];
    const float* p_b3   = (const float*)d_in[17];
    const float* oe_w   = (const float*)d_in[18];
    const float* oe_b   = (const float*)d_in[19];
    float* out = (float*)d_out;

    node_branch_kernel<<<N_TOT / 8, 256>>>(srcf, reff, counts,
                                           sg_w1, sg_b1, sg_w2, sg_b2,
                                           se_w, se_b, out);
    point_branch_kernel<<<N_TOT, 128>>>(pts, p_w1, p_b1, p_w2, p_b2,
                                        p_w3, p_b3, oe_w, oe_b, out);
}